// round 2
// baseline (speedup 1.0000x reference)
#include <cuda_runtime.h>
#include <cuda_bf16.h>
#include <math.h>

// Problem constants
#define BATCH 2
#define SEQ   2048
#define DMODEL 1024
#define NHEAD 16
#define HDIM  64
#define HALF  32
#define MROWS (BATCH * SEQ)   // 4096

// Scratch (static device globals — allocation-free rule)
__device__ float g_q[MROWS * DMODEL];
__device__ float g_k[MROWS * DMODEL];
__device__ float g_v[MROWS * DMODEL];
__device__ float g_attn[MROWS * DMODEL];

// ---------------------------------------------------------------------------
// Generic GEMM: C[M,N] = A[M,K] @ W[N,K]^T + bias[N], optional RoPE epilogue.
// M=4096, N=1024, K=1024. Tile 64x64x16, 256 threads, 4x4 per thread.
// ---------------------------------------------------------------------------
#define GM 64
#define GN 64
#define GK 16

__global__ void __launch_bounds__(256)
gemm_bias_rope_kernel(const float* __restrict__ A,
                      const float* __restrict__ W,
                      const float* __restrict__ bias,
                      float* __restrict__ C,
                      const float* __restrict__ cosb,
                      const float* __restrict__ sinb,
                      int applyRope)
{
    __shared__ float As[GK][GM + 4];
    __shared__ float Ws[GK][GN + 4];

    const int K = DMODEL;
    const int N = DMODEL;

    const int m0 = blockIdx.y * GM;
    const int n0 = blockIdx.x * GN;
    const int tid = threadIdx.x;
    const int ty = tid >> 4;       // 0..15
    const int tx = tid & 15;       // 0..15

    const int lrow = tid >> 2;       // 0..63
    const int lk4  = (tid & 3) * 4;  // 0,4,8,12

    float acc[4][4] = {};

    const float* Aload = A + (size_t)(m0 + lrow) * K + lk4;
    const float* Wload = W + (size_t)(n0 + lrow) * K + lk4;

    for (int k0 = 0; k0 < K; k0 += GK) {
        float4 av = *reinterpret_cast<const float4*>(Aload + k0);
        As[lk4 + 0][lrow] = av.x;
        As[lk4 + 1][lrow] = av.y;
        As[lk4 + 2][lrow] = av.z;
        As[lk4 + 3][lrow] = av.w;
        float4 wv = *reinterpret_cast<const float4*>(Wload + k0);
        Ws[lk4 + 0][lrow] = wv.x;
        Ws[lk4 + 1][lrow] = wv.y;
        Ws[lk4 + 2][lrow] = wv.z;
        Ws[lk4 + 3][lrow] = wv.w;
        __syncthreads();

        #pragma unroll
        for (int k = 0; k < GK; k++) {
            float a[4], b[4];
            #pragma unroll
            for (int i = 0; i < 4; i++) a[i] = As[k][ty * 4 + i];
            #pragma unroll
            for (int j = 0; j < 4; j++) b[j] = Ws[k][tx * 4 + j];
            #pragma unroll
            for (int i = 0; i < 4; i++)
                #pragma unroll
                for (int j = 0; j < 4; j++)
                    acc[i][j] = fmaf(a[i], b[j], acc[i][j]);
        }
        __syncthreads();
    }

    // epilogue: bias (+ RoPE)
    #pragma unroll
    for (int i = 0; i < 4; i++) {
        const int m = m0 + ty * 4 + i;
        const int spos = m & (SEQ - 1);
        float vals[4];
        #pragma unroll
        for (int j = 0; j < 4; j++) {
            const int n = n0 + tx * 4 + j;
            vals[j] = acc[i][j] + bias[n];
        }
        if (applyRope) {
            #pragma unroll
            for (int jp = 0; jp < 2; jp++) {
                const int n = n0 + tx * 4 + jp * 2;
                const int d = n & (HDIM - 1);
                const int fi = d >> 1;
                const float c  = cosb[spos * HALF + fi];
                const float sn = sinb[spos * HALF + fi];
                const float a = vals[jp * 2];
                const float b = vals[jp * 2 + 1];
                vals[jp * 2]     = a * c - b * sn;
                vals[jp * 2 + 1] = a * sn + b * c;
            }
        }
        #pragma unroll
        for (int j = 0; j < 4; j++) {
            const int n = n0 + tx * 4 + j;
            C[(size_t)m * N + n] = vals[j];
        }
    }
}

// ---------------------------------------------------------------------------
// Causal flash attention: one block = 128 queries of one (b, h).
// K/V tiles of 64 rows staged in smem; q and o accumulator in registers.
// Online softmax with rare-branch rescale.
// ---------------------------------------------------------------------------
#define AQ 128   // queries per block (= threads)
#define AK 64    // kv tile rows

__global__ void __launch_bounds__(AQ)
attn_kernel()
{
    __shared__ float ks[AK][HDIM];
    __shared__ float vs[AK][HDIM];

    const int b  = blockIdx.z;
    const int h  = blockIdx.y;
    const int q0 = blockIdx.x * AQ;
    const int tid = threadIdx.x;
    const int sq = q0 + tid;

    const float* qptr = g_q + ((size_t)(b * SEQ + sq) * DMODEL + h * HDIM);
    float q[HDIM];
    #pragma unroll
    for (int d4 = 0; d4 < HDIM / 4; d4++) {
        float4 t = *reinterpret_cast<const float4*>(qptr + d4 * 4);
        q[d4 * 4 + 0] = t.x * 0.125f;   // 1/sqrt(64)
        q[d4 * 4 + 1] = t.y * 0.125f;
        q[d4 * 4 + 2] = t.z * 0.125f;
        q[d4 * 4 + 3] = t.w * 0.125f;
    }

    float o[HDIM];
    #pragma unroll
    for (int d = 0; d < HDIM; d++) o[d] = 0.f;
    float mi = -1e30f, li = 0.f;

    const int ntiles = q0 / AK + 2;   // kv tiles 0 .. (q0+127)/64
    for (int t = 0; t < ntiles; t++) {
        const int kv0 = t * AK;
        const float* kbase = g_k + ((size_t)(b * SEQ + kv0) * DMODEL + h * HDIM);
        const float* vbase = g_v + ((size_t)(b * SEQ + kv0) * DMODEL + h * HDIM);
        // load 64x64 floats = 1024 float4 with 128 threads
        #pragma unroll
        for (int it = 0; it < 8; it++) {
            const int idx = tid + it * AQ;       // 0..1023
            const int r = idx >> 4;
            const int c = (idx & 15) * 4;
            *reinterpret_cast<float4*>(&ks[r][c]) =
                *reinterpret_cast<const float4*>(kbase + (size_t)r * DMODEL + c);
            *reinterpret_cast<float4*>(&vs[r][c]) =
                *reinterpret_cast<const float4*>(vbase + (size_t)r * DMODEL + c);
        }
        __syncthreads();

        const int jlim = min(AK, sq - kv0 + 1);
        for (int j = 0; j < jlim; j++) {
            float s = 0.f;
            #pragma unroll
            for (int d = 0; d < HDIM; d++) s = fmaf(q[d], ks[j][d], s);
            if (s > mi) {
                const float r = __expf(mi - s);
                li *= r;
                #pragma unroll
                for (int d = 0; d < HDIM; d++) o[d] *= r;
                mi = s;
            }
            const float p = __expf(s - mi);
            li += p;
            #pragma unroll
            for (int d = 0; d < HDIM; d++) o[d] = fmaf(p, vs[j][d], o[d]);
        }
        __syncthreads();
    }

    const float inv = 1.f / li;
    float* optr = g_attn + ((size_t)(b * SEQ + sq) * DMODEL + h * HDIM);
    #pragma unroll
    for (int d4 = 0; d4 < HDIM / 4; d4++) {
        float4 t;
        t.x = o[d4 * 4 + 0] * inv;
        t.y = o[d4 * 4 + 1] * inv;
        t.z = o[d4 * 4 + 2] * inv;
        t.w = o[d4 * 4 + 3] * inv;
        *reinterpret_cast<float4*>(optr + d4 * 4) = t;
    }
}

// ---------------------------------------------------------------------------
// Launch
// ---------------------------------------------------------------------------
extern "C" void kernel_launch(void* const* d_in, const int* in_sizes, int n_in,
                              void* d_out, int out_size)
{
    (void)in_sizes; (void)n_in; (void)out_size;
    const float* x       = (const float*)d_in[0];
    const float* pos_cos = (const float*)d_in[1];
    const float* pos_sin = (const float*)d_in[2];
    const float* wq_w    = (const float*)d_in[3];
    const float* wq_b    = (const float*)d_in[4];
    const float* wk_w    = (const float*)d_in[5];
    const float* wk_b    = (const float*)d_in[6];
    const float* wv_w    = (const float*)d_in[7];
    const float* wv_b    = (const float*)d_in[8];
    const float* wo_w    = (const float*)d_in[9];
    const float* wo_b    = (const float*)d_in[10];
    float* out = (float*)d_out;

    float *qp, *kp, *vp, *ap;
    cudaGetSymbolAddress((void**)&qp, g_q);
    cudaGetSymbolAddress((void**)&kp, g_k);
    cudaGetSymbolAddress((void**)&vp, g_v);
    cudaGetSymbolAddress((void**)&ap, g_attn);

    dim3 gg(DMODEL / GN, MROWS / GM);   // (16, 64)
    gemm_bias_rope_kernel<<<gg, 256>>>(x, wq_w, wq_b, qp, pos_cos, pos_sin, 1);
    gemm_bias_rope_kernel<<<gg, 256>>>(x, wk_w, wk_b, kp, pos_cos, pos_sin, 1);
    gemm_bias_rope_kernel<<<gg, 256>>>(x, wv_w, wv_b, vp, pos_cos, pos_sin, 0);

    dim3 ga(SEQ / AQ, NHEAD, BATCH);    // (16, 16, 2)
    attn_kernel<<<ga, AQ>>>();

    gemm_bias_rope_kernel<<<gg, 256>>>(ap, wo_w, wo_b, out, pos_cos, pos_sin, 0);
}

// round 6
// speedup vs baseline: 1.4053x; 1.4053x over previous
#include <cuda_runtime.h>
#include <cuda_bf16.h>
#include <cstdint>
#include <math.h>

// Problem constants
#define BATCH 2
#define SEQ   2048
#define DMODEL 1024
#define NHEAD 16
#define HDIM  64
#define HALF  32
#define MROWS (BATCH * SEQ)   // 4096

// Scratch (static device globals — allocation-free rule)
__device__ float g_q[MROWS * DMODEL];
__device__ float g_k[MROWS * DMODEL];
__device__ float g_v[MROWS * DMODEL];
__device__ float g_attn[MROWS * DMODEL];

__device__ __forceinline__ float tf32r(float x) {
    float r;
    asm("cvt.rna.tf32.f32 %0, %1;" : "=f"(r) : "f"(x));
    return r;
}

__device__ __forceinline__ void mma_tf32(float c[4], uint32_t a0, uint32_t a1,
                                         uint32_t a2, uint32_t a3,
                                         uint32_t b0, uint32_t b1) {
    asm volatile(
        "mma.sync.aligned.m16n8k8.row.col.f32.tf32.tf32.f32 "
        "{%0,%1,%2,%3}, {%4,%5,%6,%7}, {%8,%9}, {%0,%1,%2,%3};"
        : "+f"(c[0]), "+f"(c[1]), "+f"(c[2]), "+f"(c[3])
        : "r"(a0), "r"(a1), "r"(a2), "r"(a3), "r"(b0), "r"(b1));
}

// ---------------------------------------------------------------------------
// tf32 mma.sync GEMM: C[M,N] = A[M,K] @ W[N,K]^T + bias[N], optional RoPE.
// CTA 128x128, 8 warps (2x4), warp tile 64x32, K chunks of 32, double buffer.
// Smem row stride 36 floats -> conflict-free m16n8k8 fragment LDS.
// ---------------------------------------------------------------------------
#define BM 128
#define BN 128
#define KC 32
#define NT (DMODEL / KC)       // 32
#define AST 36                 // floats per smem row
#define TILEF (128 * AST)      // floats per tile
#define SMEM_DYN (4 * TILEF * 4)   // 4 tiles (A0,A1,B0,B1) bytes = 73728

__global__ void __launch_bounds__(256, 1)
gemm_tf32_kernel(const float* __restrict__ A,
                 const float* __restrict__ W,
                 const float* __restrict__ bias,
                 float* __restrict__ C,
                 const float* __restrict__ cosb,
                 const float* __restrict__ sinb,
                 int applyRope)
{
    extern __shared__ float ds[];
    float* aT[2] = { ds,             ds + TILEF };
    float* bT[2] = { ds + 2 * TILEF, ds + 3 * TILEF };

    const int tid = threadIdx.x;
    const int wid = tid >> 5;
    const int lid = tid & 31;
    const int wm = (wid & 1) * 64;     // warp M offset in CTA tile
    const int wn = (wid >> 1) * 32;    // warp N offset
    const int m0 = blockIdx.y * BM;
    const int n0 = blockIdx.x * BN;

    const int lrow = tid >> 3;         // 0..31 within 256: rows 0..127 over 4 iters
    const int lk4  = (tid & 7) * 4;    // 0..28

    const float* Abase = A + (size_t)m0 * DMODEL;
    const float* Wbase = W + (size_t)n0 * DMODEL;

    float4 ar[4], br[4];

    #define LOADT(kt) do {                                                    \
        _Pragma("unroll")                                                     \
        for (int _i = 0; _i < 4; _i++) {                                      \
            int _r = lrow + _i * 32;                                          \
            ar[_i] = *(const float4*)(Abase + (size_t)_r * DMODEL + (kt) * KC + lk4); \
            br[_i] = *(const float4*)(Wbase + (size_t)_r * DMODEL + (kt) * KC + lk4); \
        }                                                                     \
    } while (0)

    #define STST(buf) do {                                                    \
        _Pragma("unroll")                                                     \
        for (int _i = 0; _i < 4; _i++) {                                      \
            int _r = lrow + _i * 32;                                          \
            float4 _a = ar[_i];                                               \
            _a.x = tf32r(_a.x); _a.y = tf32r(_a.y);                           \
            _a.z = tf32r(_a.z); _a.w = tf32r(_a.w);                           \
            *(float4*)(aT[buf] + _r * AST + lk4) = _a;                        \
            float4 _b = br[_i];                                               \
            _b.x = tf32r(_b.x); _b.y = tf32r(_b.y);                           \
            _b.z = tf32r(_b.z); _b.w = tf32r(_b.w);                           \
            *(float4*)(bT[buf] + _r * AST + lk4) = _b;                        \
        }                                                                     \
    } while (0)

    float acc[4][4][4];
    #pragma unroll
    for (int i = 0; i < 4; i++)
        #pragma unroll
        for (int j = 0; j < 4; j++)
            #pragma unroll
            for (int r = 0; r < 4; r++) acc[i][j][r] = 0.f;

    const int lm = lid >> 2;          // 0..7
    const int lk = lid & 3;           // 0..3

    // prologue
    LOADT(0);
    STST(0);
    __syncthreads();
    LOADT(1);

    for (int kt = 0; kt < NT; kt++) {
        const int cur = kt & 1;
        if (kt + 1 < NT) STST(cur ^ 1);
        if (kt + 2 < NT) LOADT(kt + 2);

        const float* sa = aT[cur] + (wm + lm) * AST + lk;
        const float* sb = bT[cur] + (wn + lm) * AST + lk;
        #pragma unroll
        for (int ks = 0; ks < 4; ks++) {
            uint32_t af[4][4], bf[4][2];
            #pragma unroll
            for (int mf = 0; mf < 4; mf++) {
                af[mf][0] = __float_as_uint(sa[(mf * 16    ) * AST + ks * 8    ]);
                af[mf][1] = __float_as_uint(sa[(mf * 16 + 8) * AST + ks * 8    ]);
                af[mf][2] = __float_as_uint(sa[(mf * 16    ) * AST + ks * 8 + 4]);
                af[mf][3] = __float_as_uint(sa[(mf * 16 + 8) * AST + ks * 8 + 4]);
            }
            #pragma unroll
            for (int nf = 0; nf < 4; nf++) {
                bf[nf][0] = __float_as_uint(sb[(nf * 8) * AST + ks * 8    ]);
                bf[nf][1] = __float_as_uint(sb[(nf * 8) * AST + ks * 8 + 4]);
            }
            #pragma unroll
            for (int mf = 0; mf < 4; mf++)
                #pragma unroll
                for (int nf = 0; nf < 4; nf++)
                    mma_tf32(acc[mf][nf], af[mf][0], af[mf][1], af[mf][2], af[mf][3],
                             bf[nf][0], bf[nf][1]);
        }
        __syncthreads();
    }

    // epilogue: bias (+ RoPE), direct STG
    const int ln = (lid & 3) * 2;
    #pragma unroll
    for (int mf = 0; mf < 4; mf++) {
        #pragma unroll
        for (int half = 0; half < 2; half++) {
            const int m = m0 + wm + mf * 16 + lm + half * 8;
            const int spos = m & (SEQ - 1);
            float* crow = C + (size_t)m * DMODEL;
            #pragma unroll
            for (int nf = 0; nf < 4; nf++) {
                const int n = n0 + wn + nf * 8 + ln;
                float v0 = acc[mf][nf][half * 2 + 0] + bias[n];
                float v1 = acc[mf][nf][half * 2 + 1] + bias[n + 1];
                if (applyRope) {
                    const int fi = (n & (HDIM - 1)) >> 1;
                    const float cc = cosb[spos * HALF + fi];
                    const float ss = sinb[spos * HALF + fi];
                    const float r0 = v0 * cc - v1 * ss;
                    const float r1 = v0 * ss + v1 * cc;
                    v0 = r0; v1 = r1;
                }
                float2 st; st.x = v0; st.y = v1;
                *(float2*)(crow + n) = st;
            }
        }
    }
}

// ---------------------------------------------------------------------------
// Causal flash attention (unchanged from R1): one block = 128 queries.
// ---------------------------------------------------------------------------
#define AQ 128
#define AK 64

__global__ void __launch_bounds__(AQ)
attn_kernel()
{
    __shared__ float ks[AK][HDIM];
    __shared__ float vs[AK][HDIM];

    const int b  = blockIdx.z;
    const int h  = blockIdx.y;
    const int q0 = blockIdx.x * AQ;
    const int tid = threadIdx.x;
    const int sq = q0 + tid;

    const float* qptr = g_q + ((size_t)(b * SEQ + sq) * DMODEL + h * HDIM);
    float q[HDIM];
    #pragma unroll
    for (int d4 = 0; d4 < HDIM / 4; d4++) {
        float4 t = *reinterpret_cast<const float4*>(qptr + d4 * 4);
        q[d4 * 4 + 0] = t.x * 0.125f;
        q[d4 * 4 + 1] = t.y * 0.125f;
        q[d4 * 4 + 2] = t.z * 0.125f;
        q[d4 * 4 + 3] = t.w * 0.125f;
    }

    float o[HDIM];
    #pragma unroll
    for (int d = 0; d < HDIM; d++) o[d] = 0.f;
    float mi = -1e30f, li = 0.f;

    const int ntiles = q0 / AK + 2;
    for (int t = 0; t < ntiles; t++) {
        const int kv0 = t * AK;
        const float* kbase = g_k + ((size_t)(b * SEQ + kv0) * DMODEL + h * HDIM);
        const float* vbase = g_v + ((size_t)(b * SEQ + kv0) * DMODEL + h * HDIM);
        #pragma unroll
        for (int it = 0; it < 8; it++) {
            const int idx = tid + it * AQ;
            const int r = idx >> 4;
            const int c = (idx & 15) * 4;
            *reinterpret_cast<float4*>(&ks[r][c]) =
                *reinterpret_cast<const float4*>(kbase + (size_t)r * DMODEL + c);
            *reinterpret_cast<float4*>(&vs[r][c]) =
                *reinterpret_cast<const float4*>(vbase + (size_t)r * DMODEL + c);
        }
        __syncthreads();

        const int jlim = min(AK, sq - kv0 + 1);
        for (int j = 0; j < jlim; j++) {
            float s = 0.f;
            #pragma unroll
            for (int d = 0; d < HDIM; d++) s = fmaf(q[d], ks[j][d], s);
            if (s > mi) {
                const float r = __expf(mi - s);
                li *= r;
                #pragma unroll
                for (int d = 0; d < HDIM; d++) o[d] *= r;
                mi = s;
            }
            const float p = __expf(s - mi);
            li += p;
            #pragma unroll
            for (int d = 0; d < HDIM; d++) o[d] = fmaf(p, vs[j][d], o[d]);
        }
        __syncthreads();
    }

    const float inv = 1.f / li;
    float* optr = g_attn + ((size_t)(b * SEQ + sq) * DMODEL + h * HDIM);
    #pragma unroll
    for (int d4 = 0; d4 < HDIM / 4; d4++) {
        float4 t;
        t.x = o[d4 * 4 + 0] * inv;
        t.y = o[d4 * 4 + 1] * inv;
        t.z = o[d4 * 4 + 2] * inv;
        t.w = o[d4 * 4 + 3] * inv;
        *reinterpret_cast<float4*>(optr + d4 * 4) = t;
    }
}

// ---------------------------------------------------------------------------
// Launch
// ---------------------------------------------------------------------------
extern "C" void kernel_launch(void* const* d_in, const int* in_sizes, int n_in,
                              void* d_out, int out_size)
{
    (void)in_sizes; (void)n_in; (void)out_size;
    const float* x       = (const float*)d_in[0];
    const float* pos_cos = (const float*)d_in[1];
    const float* pos_sin = (const float*)d_in[2];
    const float* wq_w    = (const float*)d_in[3];
    const float* wq_b    = (const float*)d_in[4];
    const float* wk_w    = (const float*)d_in[5];
    const float* wk_b    = (const float*)d_in[6];
    const float* wv_w    = (const float*)d_in[7];
    const float* wv_b    = (const float*)d_in[8];
    const float* wo_w    = (const float*)d_in[9];
    const float* wo_b    = (const float*)d_in[10];
    float* out = (float*)d_out;

    float *qp, *kp, *vp, *ap;
    cudaGetSymbolAddress((void**)&qp, g_q);
    cudaGetSymbolAddress((void**)&kp, g_k);
    cudaGetSymbolAddress((void**)&vp, g_v);
    cudaGetSymbolAddress((void**)&ap, g_attn);

    cudaFuncSetAttribute(gemm_tf32_kernel,
                         cudaFuncAttributeMaxDynamicSharedMemorySize, SMEM_DYN);

    dim3 gg(DMODEL / BN, MROWS / BM);   // (8, 32)
    gemm_tf32_kernel<<<gg, 256, SMEM_DYN>>>(x, wq_w, wq_b, qp, pos_cos, pos_sin, 1);
    gemm_tf32_kernel<<<gg, 256, SMEM_DYN>>>(x, wk_w, wk_b, kp, pos_cos, pos_sin, 1);
    gemm_tf32_kernel<<<gg, 256, SMEM_DYN>>>(x, wv_w, wv_b, vp, pos_cos, pos_sin, 0);

    dim3 ga(SEQ / AQ, NHEAD, BATCH);    // (16, 16, 2)
    attn_kernel<<<ga, AQ>>>();

    gemm_tf32_kernel<<<gg, 256, SMEM_DYN>>>(ap, wo_w, wo_b, out, pos_cos, pos_sin, 0);
}

// round 7
// speedup vs baseline: 3.1218x; 2.2215x over previous
#include <cuda_runtime.h>
#include <cuda_bf16.h>
#include <cstdint>
#include <math.h>

// Problem constants
#define BATCH 2
#define SEQ   2048
#define DMODEL 1024
#define NHEAD 16
#define HDIM  64
#define HALF  32
#define MROWS (BATCH * SEQ)   // 4096

// Scratch (static device globals — allocation-free rule)
__device__ float g_q[MROWS * DMODEL];
__device__ float g_k[MROWS * DMODEL];
__device__ float g_v[MROWS * DMODEL];
__device__ float g_attn[MROWS * DMODEL];

__device__ __forceinline__ float tf32r(float x) {
    float r;
    asm("cvt.rna.tf32.f32 %0, %1;" : "=f"(r) : "f"(x));
    return r;
}

__device__ __forceinline__ void mma_tf32(float c[4], uint32_t a0, uint32_t a1,
                                         uint32_t a2, uint32_t a3,
                                         uint32_t b0, uint32_t b1) {
    asm volatile(
        "mma.sync.aligned.m16n8k8.row.col.f32.tf32.tf32.f32 "
        "{%0,%1,%2,%3}, {%4,%5,%6,%7}, {%8,%9}, {%0,%1,%2,%3};"
        : "+f"(c[0]), "+f"(c[1]), "+f"(c[2]), "+f"(c[3])
        : "r"(a0), "r"(a1), "r"(a2), "r"(a3), "r"(b0), "r"(b1));
}

// ---------------------------------------------------------------------------
// tf32 mma.sync GEMM (unchanged from R5): C = A @ W^T + bias, optional RoPE.
// ---------------------------------------------------------------------------
#define BM 128
#define BN 128
#define KC 32
#define NT (DMODEL / KC)       // 32
#define AST 36                 // floats per smem row
#define TILEF (128 * AST)
#define SMEM_DYN (4 * TILEF * 4)

__global__ void __launch_bounds__(256, 1)
gemm_tf32_kernel(const float* __restrict__ A,
                 const float* __restrict__ W,
                 const float* __restrict__ bias,
                 float* __restrict__ C,
                 const float* __restrict__ cosb,
                 const float* __restrict__ sinb,
                 int applyRope)
{
    extern __shared__ float ds[];
    float* aT[2] = { ds,             ds + TILEF };
    float* bT[2] = { ds + 2 * TILEF, ds + 3 * TILEF };

    const int tid = threadIdx.x;
    const int wid = tid >> 5;
    const int lid = tid & 31;
    const int wm = (wid & 1) * 64;
    const int wn = (wid >> 1) * 32;
    const int m0 = blockIdx.y * BM;
    const int n0 = blockIdx.x * BN;

    const int lrow = tid >> 3;
    const int lk4  = (tid & 7) * 4;

    const float* Abase = A + (size_t)m0 * DMODEL;
    const float* Wbase = W + (size_t)n0 * DMODEL;

    float4 ar[4], br[4];

    #define LOADT(kt) do {                                                    \
        _Pragma("unroll")                                                     \
        for (int _i = 0; _i < 4; _i++) {                                      \
            int _r = lrow + _i * 32;                                          \
            ar[_i] = *(const float4*)(Abase + (size_t)_r * DMODEL + (kt) * KC + lk4); \
            br[_i] = *(const float4*)(Wbase + (size_t)_r * DMODEL + (kt) * KC + lk4); \
        }                                                                     \
    } while (0)

    #define STST(buf) do {                                                    \
        _Pragma("unroll")                                                     \
        for (int _i = 0; _i < 4; _i++) {                                      \
            int _r = lrow + _i * 32;                                          \
            float4 _a = ar[_i];                                               \
            _a.x = tf32r(_a.x); _a.y = tf32r(_a.y);                           \
            _a.z = tf32r(_a.z); _a.w = tf32r(_a.w);                           \
            *(float4*)(aT[buf] + _r * AST + lk4) = _a;                        \
            float4 _b = br[_i];                                               \
            _b.x = tf32r(_b.x); _b.y = tf32r(_b.y);                           \
            _b.z = tf32r(_b.z); _b.w = tf32r(_b.w);                           \
            *(float4*)(bT[buf] + _r * AST + lk4) = _b;                        \
        }                                                                     \
    } while (0)

    float acc[4][4][4];
    #pragma unroll
    for (int i = 0; i < 4; i++)
        #pragma unroll
        for (int j = 0; j < 4; j++)
            #pragma unroll
            for (int r = 0; r < 4; r++) acc[i][j][r] = 0.f;

    const int lm = lid >> 2;
    const int lk = lid & 3;

    LOADT(0);
    STST(0);
    __syncthreads();
    LOADT(1);

    for (int kt = 0; kt < NT; kt++) {
        const int cur = kt & 1;
        if (kt + 1 < NT) STST(cur ^ 1);
        if (kt + 2 < NT) LOADT(kt + 2);

        const float* sa = aT[cur] + (wm + lm) * AST + lk;
        const float* sb = bT[cur] + (wn + lm) * AST + lk;
        #pragma unroll
        for (int ks = 0; ks < 4; ks++) {
            uint32_t af[4][4], bf[4][2];
            #pragma unroll
            for (int mf = 0; mf < 4; mf++) {
                af[mf][0] = __float_as_uint(sa[(mf * 16    ) * AST + ks * 8    ]);
                af[mf][1] = __float_as_uint(sa[(mf * 16 + 8) * AST + ks * 8    ]);
                af[mf][2] = __float_as_uint(sa[(mf * 16    ) * AST + ks * 8 + 4]);
                af[mf][3] = __float_as_uint(sa[(mf * 16 + 8) * AST + ks * 8 + 4]);
            }
            #pragma unroll
            for (int nf = 0; nf < 4; nf++) {
                bf[nf][0] = __float_as_uint(sb[(nf * 8) * AST + ks * 8    ]);
                bf[nf][1] = __float_as_uint(sb[(nf * 8) * AST + ks * 8 + 4]);
            }
            #pragma unroll
            for (int mf = 0; mf < 4; mf++)
                #pragma unroll
                for (int nf = 0; nf < 4; nf++)
                    mma_tf32(acc[mf][nf], af[mf][0], af[mf][1], af[mf][2], af[mf][3],
                             bf[nf][0], bf[nf][1]);
        }
        __syncthreads();
    }

    const int ln = (lid & 3) * 2;
    #pragma unroll
    for (int mf = 0; mf < 4; mf++) {
        #pragma unroll
        for (int half = 0; half < 2; half++) {
            const int m = m0 + wm + mf * 16 + lm + half * 8;
            const int spos = m & (SEQ - 1);
            float* crow = C + (size_t)m * DMODEL;
            #pragma unroll
            for (int nf = 0; nf < 4; nf++) {
                const int n = n0 + wn + nf * 8 + ln;
                float v0 = acc[mf][nf][half * 2 + 0] + bias[n];
                float v1 = acc[mf][nf][half * 2 + 1] + bias[n + 1];
                if (applyRope) {
                    const int fi = (n & (HDIM - 1)) >> 1;
                    const float cc = cosb[spos * HALF + fi];
                    const float ss = sinb[spos * HALF + fi];
                    const float r0 = v0 * cc - v1 * ss;
                    const float r1 = v0 * ss + v1 * cc;
                    v0 = r0; v1 = r1;
                }
                float2 st; st.x = v0; st.y = v1;
                *(float2*)(crow + n) = st;
            }
        }
    }
}

// ---------------------------------------------------------------------------
// Tensor-core flash attention (tf32 mma.sync).
// CTA = 128 queries of one (b,h); 8 warps x 16 rows; KV tiles of 64.
// ---------------------------------------------------------------------------
#define KST 68
#define VST 72
#define PST 68
#define ATTN_SMEM ((64 * KST + 64 * VST + 128 * PST) * 4)   // 70656 bytes

__global__ void __launch_bounds__(256, 1)
attn_mma_kernel()
{
    extern __shared__ float smf[];
    float* kt = smf;
    float* vt = kt + 64 * KST;
    float* pt = vt + 64 * VST;

    const int b  = blockIdx.z;
    const int h  = blockIdx.y;
    const int q0 = blockIdx.x * 128;
    const int tid = threadIdx.x;
    const int w   = tid >> 5;
    const int lid = tid & 31;
    const int lm = lid >> 2;      // 0..7
    const int lk = lid & 3;       // 0..3
    const int ln = lk * 2;        // 0,2,4,6

    // ---- stage Q (x 1/sqrt(hd), tf32) into pt, then load A-fragments ----
    const float* qg = g_q + ((size_t)(b * SEQ + q0) * DMODEL + h * HDIM);
    #pragma unroll
    for (int i = 0; i < 8; i++) {
        int idx = tid + i * 256;         // 2048 float4s = 128 rows x 16
        int row = idx >> 4;
        int c4  = (idx & 15) * 4;
        float4 v = *(const float4*)(qg + (size_t)row * DMODEL + c4);
        v.x = tf32r(v.x * 0.125f); v.y = tf32r(v.y * 0.125f);
        v.z = tf32r(v.z * 0.125f); v.w = tf32r(v.w * 0.125f);
        *(float4*)(pt + row * PST + c4) = v;
    }
    __syncthreads();

    uint32_t aq[8][4];
    {
        const float* qs = pt + (w * 16 + lm) * PST + lk;
        #pragma unroll
        for (int ks = 0; ks < 8; ks++) {
            aq[ks][0] = __float_as_uint(qs[ks * 8]);
            aq[ks][1] = __float_as_uint(qs[8 * PST + ks * 8]);
            aq[ks][2] = __float_as_uint(qs[ks * 8 + 4]);
            aq[ks][3] = __float_as_uint(qs[8 * PST + ks * 8 + 4]);
        }
    }
    // pt is next written only after the in-loop __syncthreads -> no hazard.

    float m0 = -1e30f, m1 = -1e30f, l0 = 0.f, l1 = 0.f;
    float oacc[8][4];
    #pragma unroll
    for (int nt = 0; nt < 8; nt++)
        #pragma unroll
        for (int r = 0; r < 4; r++) oacc[nt][r] = 0.f;

    const float* kg = g_k + ((size_t)(b * SEQ) * DMODEL + h * HDIM);
    const float* vg = g_v + ((size_t)(b * SEQ) * DMODEL + h * HDIM);

    const int ntiles = q0 / 64 + 2;
    for (int t = 0; t < ntiles; t++) {
        const int kv0 = t * 64;
        // cooperative K/V tile load (tf32-rounded)
        #pragma unroll
        for (int i = 0; i < 4; i++) {
            int idx = tid + i * 256;     // 1024 float4 = 64 rows x 16
            int row = idx >> 4;
            int c4  = (idx & 15) * 4;
            float4 kk = *(const float4*)(kg + (size_t)(kv0 + row) * DMODEL + c4);
            kk.x = tf32r(kk.x); kk.y = tf32r(kk.y);
            kk.z = tf32r(kk.z); kk.w = tf32r(kk.w);
            *(float4*)(kt + row * KST + c4) = kk;
            float4 vv = *(const float4*)(vg + (size_t)(kv0 + row) * DMODEL + c4);
            vv.x = tf32r(vv.x); vv.y = tf32r(vv.y);
            vv.z = tf32r(vv.z); vv.w = tf32r(vv.w);
            *(float4*)(vt + row * VST + c4) = vv;
        }
        __syncthreads();

        const bool active = !(w < 4 && t == ntiles - 1);   // warp-uniform
        if (active) {
            // ---- S = Q K^T ----
            float sacc[8][4];
            #pragma unroll
            for (int nt = 0; nt < 8; nt++)
                #pragma unroll
                for (int r = 0; r < 4; r++) sacc[nt][r] = 0.f;

            #pragma unroll
            for (int ks = 0; ks < 8; ks++) {
                #pragma unroll
                for (int nt = 0; nt < 8; nt++) {
                    uint32_t b0 = __float_as_uint(kt[(nt * 8 + lm) * KST + ks * 8 + lk]);
                    uint32_t b1 = __float_as_uint(kt[(nt * 8 + lm) * KST + ks * 8 + lk + 4]);
                    mma_tf32(sacc[nt], aq[ks][0], aq[ks][1], aq[ks][2], aq[ks][3], b0, b1);
                }
            }

            // ---- causal mask (only last two tiles cross the diagonal) ----
            if (t >= ntiles - 2) {
                const int rel0 = q0 + w * 16 + lm - kv0;
                const int rel1 = rel0 + 8;
                #pragma unroll
                for (int nt = 0; nt < 8; nt++) {
                    const int c0 = nt * 8 + ln;
                    if (c0     > rel0) sacc[nt][0] = -1e30f;
                    if (c0 + 1 > rel0) sacc[nt][1] = -1e30f;
                    if (c0     > rel1) sacc[nt][2] = -1e30f;
                    if (c0 + 1 > rel1) sacc[nt][3] = -1e30f;
                }
            }

            // ---- online softmax ----
            float rm0 = -1e30f, rm1 = -1e30f;
            #pragma unroll
            for (int nt = 0; nt < 8; nt++) {
                rm0 = fmaxf(rm0, fmaxf(sacc[nt][0], sacc[nt][1]));
                rm1 = fmaxf(rm1, fmaxf(sacc[nt][2], sacc[nt][3]));
            }
            rm0 = fmaxf(rm0, __shfl_xor_sync(0xffffffffu, rm0, 1));
            rm0 = fmaxf(rm0, __shfl_xor_sync(0xffffffffu, rm0, 2));
            rm1 = fmaxf(rm1, __shfl_xor_sync(0xffffffffu, rm1, 1));
            rm1 = fmaxf(rm1, __shfl_xor_sync(0xffffffffu, rm1, 2));

            const float mn0 = fmaxf(m0, rm0);
            const float mn1 = fmaxf(m1, rm1);
            const float sc0 = __expf(m0 - mn0);
            const float sc1 = __expf(m1 - mn1);
            m0 = mn0; m1 = mn1;
            l0 *= sc0; l1 *= sc1;
            #pragma unroll
            for (int nt = 0; nt < 8; nt++) {
                oacc[nt][0] *= sc0; oacc[nt][1] *= sc0;
                oacc[nt][2] *= sc1; oacc[nt][3] *= sc1;
            }

            float* pw = pt + (w * 16 + lm) * PST;
            #pragma unroll
            for (int nt = 0; nt < 8; nt++) {
                const float p0 = __expf(sacc[nt][0] - m0);
                const float p1 = __expf(sacc[nt][1] - m0);
                const float p2 = __expf(sacc[nt][2] - m1);
                const float p3 = __expf(sacc[nt][3] - m1);
                l0 += p0 + p1;
                l1 += p2 + p3;
                *(float2*)(pw + nt * 8 + ln)           = make_float2(p0, p1);
                *(float2*)(pw + 8 * PST + nt * 8 + ln) = make_float2(p2, p3);
            }
            __syncwarp();

            // ---- O += P V ----
            const float* pa = pt + (w * 16 + lm) * PST + lk;
            #pragma unroll
            for (int ks = 0; ks < 8; ks++) {
                const uint32_t a0 = __float_as_uint(pa[ks * 8]);
                const uint32_t a1 = __float_as_uint(pa[8 * PST + ks * 8]);
                const uint32_t a2 = __float_as_uint(pa[ks * 8 + 4]);
                const uint32_t a3 = __float_as_uint(pa[8 * PST + ks * 8 + 4]);
                #pragma unroll
                for (int nt = 0; nt < 8; nt++) {
                    uint32_t b0 = __float_as_uint(vt[(ks * 8 + lk) * VST + nt * 8 + lm]);
                    uint32_t b1 = __float_as_uint(vt[(ks * 8 + lk + 4) * VST + nt * 8 + lm]);
                    mma_tf32(oacc[nt], a0, a1, a2, a3, b0, b1);
                }
            }
        }
        __syncthreads();
    }

    // ---- finalize ----
    l0 += __shfl_xor_sync(0xffffffffu, l0, 1);
    l0 += __shfl_xor_sync(0xffffffffu, l0, 2);
    l1 += __shfl_xor_sync(0xffffffffu, l1, 1);
    l1 += __shfl_xor_sync(0xffffffffu, l1, 2);
    const float inv0 = 1.f / l0;
    const float inv1 = 1.f / l1;

    float* og = g_attn + ((size_t)(b * SEQ + q0 + w * 16 + lm) * DMODEL + h * HDIM);
    #pragma unroll
    for (int nt = 0; nt < 8; nt++) {
        *(float2*)(og + nt * 8 + ln) =
            make_float2(oacc[nt][0] * inv0, oacc[nt][1] * inv0);
        *(float2*)(og + 8 * DMODEL + nt * 8 + ln) =
            make_float2(oacc[nt][2] * inv1, oacc[nt][3] * inv1);
    }
}

// ---------------------------------------------------------------------------
// Launch
// ---------------------------------------------------------------------------
extern "C" void kernel_launch(void* const* d_in, const int* in_sizes, int n_in,
                              void* d_out, int out_size)
{
    (void)in_sizes; (void)n_in; (void)out_size;
    const float* x       = (const float*)d_in[0];
    const float* pos_cos = (const float*)d_in[1];
    const float* pos_sin = (const float*)d_in[2];
    const float* wq_w    = (const float*)d_in[3];
    const float* wq_b    = (const float*)d_in[4];
    const float* wk_w    = (const float*)d_in[5];
    const float* wk_b    = (const float*)d_in[6];
    const float* wv_w    = (const float*)d_in[7];
    const float* wv_b    = (const float*)d_in[8];
    const float* wo_w    = (const float*)d_in[9];
    const float* wo_b    = (const float*)d_in[10];
    float* out = (float*)d_out;

    float *qp, *kp, *vp, *ap;
    cudaGetSymbolAddress((void**)&qp, g_q);
    cudaGetSymbolAddress((void**)&kp, g_k);
    cudaGetSymbolAddress((void**)&vp, g_v);
    cudaGetSymbolAddress((void**)&ap, g_attn);

    cudaFuncSetAttribute(gemm_tf32_kernel,
                         cudaFuncAttributeMaxDynamicSharedMemorySize, SMEM_DYN);
    cudaFuncSetAttribute(attn_mma_kernel,
                         cudaFuncAttributeMaxDynamicSharedMemorySize, ATTN_SMEM);

    dim3 gg(DMODEL / BN, MROWS / BM);   // (8, 32)
    gemm_tf32_kernel<<<gg, 256, SMEM_DYN>>>(x, wq_w, wq_b, qp, pos_cos, pos_sin, 1);
    gemm_tf32_kernel<<<gg, 256, SMEM_DYN>>>(x, wk_w, wk_b, kp, pos_cos, pos_sin, 1);
    gemm_tf32_kernel<<<gg, 256, SMEM_DYN>>>(x, wv_w, wv_b, vp, pos_cos, pos_sin, 0);

    dim3 ga(SEQ / 128, NHEAD, BATCH);   // (16, 16, 2)
    attn_mma_kernel<<<ga, 256, ATTN_SMEM>>>();

    gemm_tf32_kernel<<<gg, 256, SMEM_DYN>>>(ap, wo_w, wo_b, out, pos_cos, pos_sin, 0);
}